// round 3
// baseline (speedup 1.0000x reference)
#include <cuda_runtime.h>
#include <math.h>

// ---- problem constants ----
#define B_   16
#define L_   128
#define O_   128
#define N_   256
#define S_   64
#define U_   32
#define DEL  64
#define HID  512
#define KC   4
#define CDIM 288           // N_ + U_
#define DOUT 24640         // DEL + N_*U_ + N_*S_
#define TOK  2048          // B_ * L_
#define KDIM 288

// ---- scratch (device globals: no allocation allowed) ----
__device__ float g_p[TOK * N_];        // proj outputs, tokens 0..127 per batch (incl. z0 @127)
__device__ float g_old[TOK * CDIM];    // post-conv silu activations
__device__ float g_gen[TOK * DOUT];    // big GEMM output (~202 MB)
__device__ float g_dA[TOK * N_];
__device__ float g_coeff[TOK * N_];
__device__ float g_Bu[TOK * N_];
__device__ float g_z[TOK * N_];
__device__ float g_part[TOK];          // per-token squared-error partial sums

__device__ __forceinline__ float siluf(float v) { return v / (1.0f + expf(-v)); }

// ------------------------------------------------------------------
// K1: proj_x(v) = relu(v @ W0^T + b0) @ W1^T + b1 for tokens 0..127 of x.
// Block = (batch, 8-token tile); 256 threads.
// ------------------------------------------------------------------
__global__ void __launch_bounds__(256) k_proj(const float* __restrict__ x,
                                              const float* __restrict__ W0,
                                              const float* __restrict__ b0,
                                              const float* __restrict__ W1,
                                              const float* __restrict__ b1) {
    __shared__ float xs[8][64];
    __shared__ float hs[8][512];
    int b  = blockIdx.x >> 4;
    int t0 = (blockIdx.x & 15) * 8;
    int tid = threadIdx.x;

    for (int i = tid; i < 8 * 64; i += 256) {
        int tt = i >> 6, k = i & 63;
        xs[tt][k] = x[(b * (O_ + L_) + t0 + tt) * S_ + k];
    }
    __syncthreads();

    // hidden layer
    #pragma unroll
    for (int jj = 0; jj < 2; jj++) {
        int j = tid + jj * 256;
        float acc[8];
        float bj = b0[j];
        #pragma unroll
        for (int tt = 0; tt < 8; tt++) acc[tt] = bj;
        for (int k = 0; k < 64; k++) {
            float w = W0[j * 64 + k];
            #pragma unroll
            for (int tt = 0; tt < 8; tt++) acc[tt] += w * xs[tt][k];
        }
        #pragma unroll
        for (int tt = 0; tt < 8; tt++) hs[tt][j] = fmaxf(acc[tt], 0.0f);
    }
    __syncthreads();

    // output layer
    int n = tid;
    float acc2[8];
    float bn = b1[n];
    #pragma unroll
    for (int tt = 0; tt < 8; tt++) acc2[tt] = bn;
    for (int j = 0; j < 512; j++) {
        float w = W1[n * 512 + j];
        #pragma unroll
        for (int tt = 0; tt < 8; tt++) acc2[tt] += w * hs[tt][j];
    }
    #pragma unroll
    for (int tt = 0; tt < 8; tt++) g_p[(b * L_ + t0 + tt) * N_ + n] = acc2[tt];
}

// ------------------------------------------------------------------
// K2: silu -> depthwise conv (K=4, pad 3/3, keep last 128 outputs) -> silu.
// old[b,l,c] = silu(cb[c] + sum_k cw[c,k] * silu(seq[b, l+k-1, c])), valid idx 0..126
// seq channel c<256 from proj, c>=256 from u.
// ------------------------------------------------------------------
__global__ void k_conv(const float* __restrict__ u,
                       const float* __restrict__ cw,
                       const float* __restrict__ cb) {
    int tok = blockIdx.x;
    int b = tok >> 7, l = tok & 127;
    int c = threadIdx.x;   // 0..287
    float acc = cb[c];
    #pragma unroll
    for (int k = 0; k < KC; k++) {
        int i = l - 1 + k;
        if (i >= 0 && i <= 126) {
            float v = (c < 256) ? g_p[((b << 7) + i) * N_ + c]
                                : u[(b * 256 + i) * U_ + (c - 256)];
            acc += cw[c * 4 + k] * siluf(v);
        }
    }
    g_old[tok * CDIM + c] = siluf(acc);
}

// ------------------------------------------------------------------
// K3: big SGEMM: g_gen[m][n] = bg[n] + sum_k g_old[m][k] * Wg[n][k]
// M=2048, N=24640, K=288.  BM=BN=128, BK=32, 8x8 microtiles, 256 threads.
// ------------------------------------------------------------------
__global__ void __launch_bounds__(256) k_gemm(const float* __restrict__ Wg,
                                              const float* __restrict__ bg) {
    __shared__ float As[32][132];
    __shared__ float Bs[32][132];
    int m0 = blockIdx.y * 128;
    int n0 = blockIdx.x * 128;
    int tid = threadIdx.x;
    int tx = tid & 15, ty = tid >> 4;

    float acc[8][8];
    #pragma unroll
    for (int i = 0; i < 8; i++)
        #pragma unroll
        for (int j = 0; j < 8; j++) acc[i][j] = 0.0f;

    for (int k0 = 0; k0 < KDIM; k0 += 32) {
        #pragma unroll
        for (int p = 0; p < 4; p++) {
            int f4 = tid + p * 256;
            int row = f4 >> 3, c4 = (f4 & 7) * 4;
            float4 v = *reinterpret_cast<const float4*>(&g_old[(m0 + row) * KDIM + k0 + c4]);
            As[c4 + 0][row] = v.x; As[c4 + 1][row] = v.y;
            As[c4 + 2][row] = v.z; As[c4 + 3][row] = v.w;
        }
        #pragma unroll
        for (int p = 0; p < 4; p++) {
            int f4 = tid + p * 256;
            int row = f4 >> 3, c4 = (f4 & 7) * 4;
            float4 v = make_float4(0.f, 0.f, 0.f, 0.f);
            if (n0 + row < DOUT)
                v = *reinterpret_cast<const float4*>(&Wg[(n0 + row) * KDIM + k0 + c4]);
            Bs[c4 + 0][row] = v.x; Bs[c4 + 1][row] = v.y;
            Bs[c4 + 2][row] = v.z; Bs[c4 + 3][row] = v.w;
        }
        __syncthreads();

        #pragma unroll
        for (int k = 0; k < 32; k++) {
            float a[8], bf[8];
            #pragma unroll
            for (int i = 0; i < 8; i++) a[i]  = As[k][ty * 8 + i];
            #pragma unroll
            for (int j = 0; j < 8; j++) bf[j] = Bs[k][tx * 8 + j];
            #pragma unroll
            for (int i = 0; i < 8; i++)
                #pragma unroll
                for (int j = 0; j < 8; j++) acc[i][j] += a[i] * bf[j];
        }
        __syncthreads();
    }

    #pragma unroll
    for (int j = 0; j < 8; j++) {
        int col = n0 + tx * 8 + j;
        if (col < DOUT) {
            float bb = bg[col];
            #pragma unroll
            for (int i = 0; i < 8; i++)
                g_gen[(size_t)(m0 + ty * 8 + i) * DOUT + col] = acc[i][j] + bb;
        }
    }
}

// ------------------------------------------------------------------
// K4: delta path: delta = softplus(gen[:, :64] @ Wdt^T + bdt);
//     a = -(A>0 ? A : expm1(A)); dA = exp(delta*a); coeff = (dA-1)/a
// ------------------------------------------------------------------
__global__ void k_delta(const float* __restrict__ A,
                        const float* __restrict__ Wdt,
                        const float* __restrict__ bdt) {
    __shared__ float d[64];
    int tok = blockIdx.x;
    int tid = threadIdx.x;
    if (tid < 64) d[tid] = g_gen[(size_t)tok * DOUT + tid];
    __syncthreads();
    int n = tid;
    float acc = bdt[n];
    #pragma unroll 8
    for (int k = 0; k < 64; k++) acc += d[k] * Wdt[n * 64 + k];
    // stable softplus = max(x,0) + log1p(exp(-|x|))
    float sp = fmaxf(acc, 0.0f) + log1pf(expf(-fabsf(acc)));
    float a = A[n];
    float an = (a > 0.0f) ? -a : -expm1f(a);
    float dA = expf(sp * an);
    g_dA[tok * N_ + n] = dA;
    g_coeff[tok * N_ + n] = (dA - 1.0f) / an;
}

// ------------------------------------------------------------------
// K5: Bu[tok][n] = coeff * sum_u Bm[tok][n][u] * u0[tok][u]
//     Bm at gen cols 64 + n*32 + u ; u0 = u[b, 127+t, :]
// ------------------------------------------------------------------
__global__ void k_bu(const float* __restrict__ u) {
    __shared__ float us[32];
    int tok = blockIdx.x;
    int b = tok >> 7, t = tok & 127;
    int tid = threadIdx.x;
    if (tid < 32) us[tid] = u[(b * 256 + 127 + t) * U_ + tid];
    __syncthreads();
    const float* gp = &g_gen[(size_t)tok * DOUT + DEL + tid * U_];
    float acc = 0.0f;
    #pragma unroll
    for (int uu = 0; uu < 32; uu++) acc += gp[uu] * us[uu];
    g_Bu[tok * N_ + tid] = g_coeff[tok * N_ + tid] * acc;
}

// ------------------------------------------------------------------
// K6: sequential scan over t: z = z*dA + Bu, starting from z0 = proj(x[:,127,:])
// ------------------------------------------------------------------
__global__ void k_scan() {
    int b = blockIdx.x;
    int n = threadIdx.x;
    float z = g_p[((b << 7) + 127) * N_ + n];
    for (int t = 0; t < L_; t++) {
        int idx = ((b << 7) + t) * N_ + n;
        z = z * g_dA[idx] + g_Bu[idx];
        g_z[idx] = z;
    }
}

// ------------------------------------------------------------------
// K7: y[b,t,s] = sum_n Cm[tok][n][s] * z[tok][n], Cm at gen col 8256+n*64+s.
//     Writes ys in (t, b, s) order at out[1 + ...]; per-token sq-err partial.
// ------------------------------------------------------------------
__global__ void k_y(const float* __restrict__ x, float* __restrict__ out) {
    __shared__ float zs[256];
    __shared__ float red[2];
    int tok = blockIdx.x;
    int b = tok >> 7, t = tok & 127;
    int s = threadIdx.x;   // 0..63
    for (int i = s; i < 256; i += 64) zs[i] = g_z[tok * N_ + i];
    __syncthreads();
    const float* gp = &g_gen[(size_t)tok * DOUT + DEL + N_ * U_ + s];
    float acc = 0.0f;
    #pragma unroll 8
    for (int n = 0; n < 256; n++) acc += gp[n * 64] * zs[n];
    out[1 + ((t << 4) + b) * S_ + s] = acc;
    float diff = acc - x[(b * 256 + 128 + t) * S_ + s];
    float v = diff * diff;
    #pragma unroll
    for (int o = 16; o > 0; o >>= 1) v += __shfl_down_sync(0xffffffffu, v, o);
    if ((s & 31) == 0) red[s >> 5] = v;
    __syncthreads();
    if (s == 0) g_part[tok] = red[0] + red[1];
}

// ------------------------------------------------------------------
// K8: loss = sum(partials) / (B*S*L)   (mean over (B,S) per step, sum_t / L)
// ------------------------------------------------------------------
__global__ void k_loss(float* __restrict__ out) {
    __shared__ float red[256];
    float v = 0.0f;
    for (int i = threadIdx.x; i < TOK; i += 256) v += g_part[i];
    red[threadIdx.x] = v;
    __syncthreads();
    for (int st = 128; st > 0; st >>= 1) {
        if (threadIdx.x < st) red[threadIdx.x] += red[threadIdx.x + st];
        __syncthreads();
    }
    if (threadIdx.x == 0) out[0] = red[0] / (float)(B_ * S_ * L_);
}

// ------------------------------------------------------------------
extern "C" void kernel_launch(void* const* d_in, const int* in_sizes, int n_in,
                              void* d_out, int out_size) {
    const float* x   = (const float*)d_in[0];
    const float* u   = (const float*)d_in[1];
    const float* A   = (const float*)d_in[2];
    const float* W0  = (const float*)d_in[3];
    const float* b0  = (const float*)d_in[4];
    const float* W1  = (const float*)d_in[5];
    const float* b1  = (const float*)d_in[6];
    const float* cw  = (const float*)d_in[7];
    const float* cb  = (const float*)d_in[8];
    const float* Wg  = (const float*)d_in[9];
    const float* bg  = (const float*)d_in[10];
    const float* Wdt = (const float*)d_in[11];
    const float* bdt = (const float*)d_in[12];
    float* out = (float*)d_out;

    k_proj<<<256, 256>>>(x, W0, b0, W1, b1);
    k_conv<<<TOK, CDIM>>>(u, cw, cb);
    dim3 gg((DOUT + 127) / 128, TOK / 128);   // (193, 16)
    k_gemm<<<gg, 256>>>(Wg, bg);
    k_delta<<<TOK, 256>>>(A, Wdt, bdt);
    k_bu<<<TOK, 256>>>(u);
    k_scan<<<B_, N_>>>();
    k_y<<<TOK, S_>>>(x, out);
    k_loss<<<1, 256>>>(out);
}

// round 4
// speedup vs baseline: 1.1107x; 1.1107x over previous
#include <cuda_runtime.h>
#include <math.h>

// ---- problem constants ----
#define B_   16
#define L_   128
#define O_   128
#define N_   256
#define S_   64
#define U_   32
#define DEL  64
#define HID  512
#define KC   4
#define CDIM 288           // N_ + U_
#define DOUT 24640         // DEL + N_*U_ + N_*S_
#define TOK  2048          // B_ * L_
#define KDIM 288

// ---- scratch (device globals: no allocation allowed) ----
__device__ float g_p[TOK * N_];        // proj outputs (incl. z0 @127)
__device__ float g_old[TOK * CDIM];    // post-conv silu activations
__device__ float g_gen[TOK * DOUT];    // big GEMM output (~202 MB)
__device__ float g_dA[TOK * N_];
__device__ float g_coeff[TOK * N_];
__device__ float g_Bu[TOK * N_];
__device__ float g_z[TOK * N_];
__device__ float g_part[TOK];          // per-token squared-error partials

__device__ __forceinline__ float siluf(float v) { return v / (1.0f + expf(-v)); }

// ------------------------------------------------------------------
// K1: proj_x(v) = relu(v @ W0^T + b0) @ W1^T + b1 for tokens 0..127 of x.
// ------------------------------------------------------------------
__global__ void __launch_bounds__(256) k_proj(const float* __restrict__ x,
                                              const float* __restrict__ W0,
                                              const float* __restrict__ b0,
                                              const float* __restrict__ W1,
                                              const float* __restrict__ b1) {
    __shared__ float xs[8][64];
    __shared__ float hs[8][512];
    int b  = blockIdx.x >> 4;
    int t0 = (blockIdx.x & 15) * 8;
    int tid = threadIdx.x;

    for (int i = tid; i < 8 * 64; i += 256) {
        int tt = i >> 6, k = i & 63;
        xs[tt][k] = x[(b * (O_ + L_) + t0 + tt) * S_ + k];
    }
    __syncthreads();

    #pragma unroll
    for (int jj = 0; jj < 2; jj++) {
        int j = tid + jj * 256;
        float acc[8];
        float bj = b0[j];
        #pragma unroll
        for (int tt = 0; tt < 8; tt++) acc[tt] = bj;
        for (int k = 0; k < 64; k++) {
            float w = W0[j * 64 + k];
            #pragma unroll
            for (int tt = 0; tt < 8; tt++) acc[tt] += w * xs[tt][k];
        }
        #pragma unroll
        for (int tt = 0; tt < 8; tt++) hs[tt][j] = fmaxf(acc[tt], 0.0f);
    }
    __syncthreads();

    int n = tid;
    float acc2[8];
    float bn = b1[n];
    #pragma unroll
    for (int tt = 0; tt < 8; tt++) acc2[tt] = bn;
    for (int j = 0; j < 512; j++) {
        float w = W1[n * 512 + j];
        #pragma unroll
        for (int tt = 0; tt < 8; tt++) acc2[tt] += w * hs[tt][j];
    }
    #pragma unroll
    for (int tt = 0; tt < 8; tt++) g_p[(b * L_ + t0 + tt) * N_ + n] = acc2[tt];
}

// ------------------------------------------------------------------
// K2: silu -> depthwise conv (K=4) -> silu.
// ------------------------------------------------------------------
__global__ void k_conv(const float* __restrict__ u,
                       const float* __restrict__ cw,
                       const float* __restrict__ cb) {
    int tok = blockIdx.x;
    int b = tok >> 7, l = tok & 127;
    int c = threadIdx.x;   // 0..287
    float acc = cb[c];
    #pragma unroll
    for (int k = 0; k < KC; k++) {
        int i = l - 1 + k;
        if (i >= 0 && i <= 126) {
            float v = (c < 256) ? g_p[((b << 7) + i) * N_ + c]
                                : u[(b * 256 + i) * U_ + (c - 256)];
            acc += cw[c * 4 + k] * siluf(v);
        }
    }
    g_old[tok * CDIM + c] = siluf(acc);
}

// ------------------------------------------------------------------
// K3: big SGEMM with register-staged prefetch.
// g_gen[m][n] = bg[n] + sum_k g_old[m][k] * Wg[n][k]
// M=2048, N=24640, K=288.  BM=BN=128, BK=32, 8x8 microtiles, 256 threads.
// Next tile's LDGs issue before the compute loop -> latency hidden by FFMA.
// ------------------------------------------------------------------
__global__ void __launch_bounds__(256) k_gemm(const float* __restrict__ Wg,
                                              const float* __restrict__ bg) {
    __shared__ float As[32][132];
    __shared__ float Bs[32][132];
    int m0 = blockIdx.y * 128;
    int n0 = blockIdx.x * 128;
    int tid = threadIdx.x;
    int tx = tid & 15, ty = tid >> 4;

    float4 ra[4], rb[4];
    float acc[8][8];
    #pragma unroll
    for (int i = 0; i < 8; i++)
        #pragma unroll
        for (int j = 0; j < 8; j++) acc[i][j] = 0.0f;

    // prefetch tile 0 into registers
    #pragma unroll
    for (int p = 0; p < 4; p++) {
        int f4 = tid + p * 256;
        int row = f4 >> 3, c4 = (f4 & 7) * 4;
        ra[p] = *reinterpret_cast<const float4*>(&g_old[(m0 + row) * KDIM + c4]);
        rb[p] = (n0 + row < DOUT)
              ? *reinterpret_cast<const float4*>(&Wg[(size_t)(n0 + row) * KDIM + c4])
              : make_float4(0.f, 0.f, 0.f, 0.f);
    }

    #pragma unroll 1
    for (int it = 0; it < 9; it++) {
        // store staged registers to smem (transposed)
        #pragma unroll
        for (int p = 0; p < 4; p++) {
            int f4 = tid + p * 256;
            int row = f4 >> 3, c4 = (f4 & 7) * 4;
            As[c4 + 0][row] = ra[p].x; As[c4 + 1][row] = ra[p].y;
            As[c4 + 2][row] = ra[p].z; As[c4 + 3][row] = ra[p].w;
            Bs[c4 + 0][row] = rb[p].x; Bs[c4 + 1][row] = rb[p].y;
            Bs[c4 + 2][row] = rb[p].z; Bs[c4 + 3][row] = rb[p].w;
        }
        __syncthreads();

        // issue LDGs for next tile before computing this one
        if (it < 8) {
            int k0 = (it + 1) * 32;
            #pragma unroll
            for (int p = 0; p < 4; p++) {
                int f4 = tid + p * 256;
                int row = f4 >> 3, c4 = (f4 & 7) * 4;
                ra[p] = *reinterpret_cast<const float4*>(&g_old[(m0 + row) * KDIM + k0 + c4]);
                rb[p] = (n0 + row < DOUT)
                      ? *reinterpret_cast<const float4*>(&Wg[(size_t)(n0 + row) * KDIM + k0 + c4])
                      : make_float4(0.f, 0.f, 0.f, 0.f);
            }
        }

        #pragma unroll
        for (int k = 0; k < 32; k++) {
            float4 a0 = *reinterpret_cast<const float4*>(&As[k][ty * 8]);
            float4 a1 = *reinterpret_cast<const float4*>(&As[k][ty * 8 + 4]);
            float4 b0 = *reinterpret_cast<const float4*>(&Bs[k][tx * 8]);
            float4 b1 = *reinterpret_cast<const float4*>(&Bs[k][tx * 8 + 4]);
            float a[8] = {a0.x, a0.y, a0.z, a0.w, a1.x, a1.y, a1.z, a1.w};
            float bf[8] = {b0.x, b0.y, b0.z, b0.w, b1.x, b1.y, b1.z, b1.w};
            #pragma unroll
            for (int i = 0; i < 8; i++)
                #pragma unroll
                for (int j = 0; j < 8; j++) acc[i][j] += a[i] * bf[j];
        }
        __syncthreads();
    }

    #pragma unroll
    for (int j = 0; j < 8; j++) {
        int col = n0 + tx * 8 + j;
        if (col < DOUT) {
            float bb = bg[col];
            #pragma unroll
            for (int i = 0; i < 8; i++)
                g_gen[(size_t)(m0 + ty * 8 + i) * DOUT + col] = acc[i][j] + bb;
        }
    }
}

// ------------------------------------------------------------------
// K4: delta path via warp-shuffle reduction (coalesced Wdt reads).
// One warp per token; lane k-slices the 64-length dot products.
// delta = softplus(gen[:, :64] @ Wdt^T + bdt);
// a = -(A>0 ? A : expm1(A)); dA = exp(delta*a); coeff = (dA-1)/a
// ------------------------------------------------------------------
__global__ void __launch_bounds__(128) k_delta(const float* __restrict__ A,
                                               const float* __restrict__ Wdt,
                                               const float* __restrict__ bdt) {
    int tok = blockIdx.x * 4 + (threadIdx.x >> 5);
    int lane = threadIdx.x & 31;
    const float* gp = &g_gen[(size_t)tok * DOUT];
    float dlo = gp[lane];
    float dhi = gp[32 + lane];

    float res[8];
    #pragma unroll
    for (int g = 0; g < 8; g++) {
        float myres = 0.0f;
        #pragma unroll
        for (int j = 0; j < 32; j++) {
            int n = g * 32 + j;
            float p = dlo * Wdt[n * 64 + lane] + dhi * Wdt[n * 64 + 32 + lane];
            #pragma unroll
            for (int o = 16; o > 0; o >>= 1)
                p += __shfl_xor_sync(0xffffffffu, p, o);
            if (lane == j) myres = p;
        }
        res[g] = myres;
    }
    #pragma unroll
    for (int g = 0; g < 8; g++) {
        int n = g * 32 + lane;
        float acc = res[g] + bdt[n];
        float sp = fmaxf(acc, 0.0f) + log1pf(expf(-fabsf(acc)));
        float a = A[n];
        float an = (a > 0.0f) ? -a : -expm1f(a);
        float dA = expf(sp * an);
        g_dA[tok * N_ + n] = dA;
        g_coeff[tok * N_ + n] = (dA - 1.0f) / an;
    }
}

// ------------------------------------------------------------------
// K5: Bu[tok][n] = coeff * sum_u Bm[tok][n][u] * u0[tok][u]
// Coalesced float4 loads of Bm into padded smem, conflict-free compute.
// ------------------------------------------------------------------
__global__ void __launch_bounds__(256) k_bu(const float* __restrict__ u) {
    __shared__ float sB[256 * 33];
    __shared__ float us[32];
    int tok = blockIdx.x;
    int b = tok >> 7, t = tok & 127;
    int tid = threadIdx.x;
    if (tid < 32) us[tid] = u[(b * 256 + 127 + t) * U_ + tid];
    const float4* src = reinterpret_cast<const float4*>(&g_gen[(size_t)tok * DOUT + DEL]);
    #pragma unroll
    for (int q = 0; q < 8; q++) {
        int e4 = tid + q * 256;            // 0..2047, 4 floats each
        float4 v = src[e4];
        int n  = e4 >> 3;                  // (e4*4)/32
        int u0 = (e4 & 7) * 4;
        float* dst = &sB[n * 33 + u0];
        dst[0] = v.x; dst[1] = v.y; dst[2] = v.z; dst[3] = v.w;
    }
    __syncthreads();
    float acc = 0.0f;
    #pragma unroll
    for (int uu = 0; uu < 32; uu++) acc += sB[tid * 33 + uu] * us[uu];
    g_Bu[tok * N_ + tid] = g_coeff[tok * N_ + tid] * acc;
}

// ------------------------------------------------------------------
// K6: sequential scan, unroll-8 batched loads for MLP.
// ------------------------------------------------------------------
__global__ void k_scan() {
    int b = blockIdx.x;
    int n = threadIdx.x;
    float z = g_p[((b << 7) + 127) * N_ + n];
    for (int t0 = 0; t0 < L_; t0 += 8) {
        float da[8], bu[8];
        #pragma unroll
        for (int q = 0; q < 8; q++) {
            int idx = ((b << 7) + t0 + q) * N_ + n;
            da[q] = g_dA[idx];
            bu[q] = g_Bu[idx];
        }
        #pragma unroll
        for (int q = 0; q < 8; q++) {
            z = z * da[q] + bu[q];
            g_z[((b << 7) + t0 + q) * N_ + n] = z;
        }
    }
}

// ------------------------------------------------------------------
// K7: y[b,t,s] = sum_n Cm[tok][n][s] * z[tok][n]; sq-err partials.
// ------------------------------------------------------------------
__global__ void k_y(const float* __restrict__ x, float* __restrict__ out) {
    __shared__ float zs[256];
    __shared__ float red[2];
    int tok = blockIdx.x;
    int b = tok >> 7, t = tok & 127;
    int s = threadIdx.x;   // 0..63
    for (int i = s; i < 256; i += 64) zs[i] = g_z[tok * N_ + i];
    __syncthreads();
    const float* gp = &g_gen[(size_t)tok * DOUT + DEL + N_ * U_ + s];
    float acc = 0.0f;
    #pragma unroll 8
    for (int n = 0; n < 256; n++) acc += gp[n * 64] * zs[n];
    out[1 + ((t << 4) + b) * S_ + s] = acc;
    float diff = acc - x[(b * 256 + 128 + t) * S_ + s];
    float v = diff * diff;
    #pragma unroll
    for (int o = 16; o > 0; o >>= 1) v += __shfl_down_sync(0xffffffffu, v, o);
    if ((s & 31) == 0) red[s >> 5] = v;
    __syncthreads();
    if (s == 0) g_part[tok] = red[0] + red[1];
}

// ------------------------------------------------------------------
// K8: loss reduction.
// ------------------------------------------------------------------
__global__ void k_loss(float* __restrict__ out) {
    __shared__ float red[256];
    float v = 0.0f;
    for (int i = threadIdx.x; i < TOK; i += 256) v += g_part[i];
    red[threadIdx.x] = v;
    __syncthreads();
    for (int st = 128; st > 0; st >>= 1) {
        if (threadIdx.x < st) red[threadIdx.x] += red[threadIdx.x + st];
        __syncthreads();
    }
    if (threadIdx.x == 0) out[0] = red[0] / (float)(B_ * S_ * L_);
}

// ------------------------------------------------------------------
extern "C" void kernel_launch(void* const* d_in, const int* in_sizes, int n_in,
                              void* d_out, int out_size) {
    const float* x   = (const float*)d_in[0];
    const float* u   = (const float*)d_in[1];
    const float* A   = (const float*)d_in[2];
    const float* W0  = (const float*)d_in[3];
    const float* b0  = (const float*)d_in[4];
    const float* W1  = (const float*)d_in[5];
    const float* b1  = (const float*)d_in[6];
    const float* cw  = (const float*)d_in[7];
    const float* cb  = (const float*)d_in[8];
    const float* Wg  = (const float*)d_in[9];
    const float* bg  = (const float*)d_in[10];
    const float* Wdt = (const float*)d_in[11];
    const float* bdt = (const float*)d_in[12];
    float* out = (float*)d_out;

    k_proj<<<256, 256>>>(x, W0, b0, W1, b1);
    k_conv<<<TOK, CDIM>>>(u, cw, cb);
    dim3 gg((DOUT + 127) / 128, TOK / 128);   // (193, 16)
    k_gemm<<<gg, 256>>>(Wg, bg);
    k_delta<<<TOK / 4, 128>>>(A, Wdt, bdt);
    k_bu<<<TOK, 256>>>(u);
    k_scan<<<B_, N_>>>();
    k_y<<<TOK, S_>>>(x, out);
    k_loss<<<1, 256>>>(out);
}

// round 6
// speedup vs baseline: 2.2459x; 2.0222x over previous
#include <cuda_runtime.h>
#include <math.h>
#include <stdint.h>

// ---- problem constants ----
#define B_   16
#define L_   128
#define O_   128
#define N_   256
#define S_   64
#define U_   32
#define DEL  64
#define HID  512
#define KC   4
#define CDIM 288           // N_ + U_
#define DOUT 24640         // DEL + N_*U_ + N_*S_
#define TOK  2048          // B_ * L_
#define KDIM 288

// ---- scratch (device globals: no allocation allowed) ----
__device__ float g_p[TOK * N_];
__device__ float g_old[TOK * CDIM];
__device__ float g_gen[(size_t)TOK * DOUT];
__device__ float g_dA[TOK * N_];
__device__ float g_coeff[TOK * N_];
__device__ float g_Bu[TOK * N_];
__device__ float g_z[TOK * N_];
__device__ float g_part[TOK];

__device__ __forceinline__ float siluf(float v) { return v / (1.0f + expf(-v)); }

__device__ __forceinline__ uint32_t tf32r(float f) {
    uint32_t r; asm("cvt.rna.tf32.f32 %0, %1;" : "=r"(r) : "f"(f)); return r;
}

// m16n8k8 tf32 tensor-core MMA (Ampere-class PTX; compiles for plain sm_103)
__device__ __forceinline__ void mma8(float* c, const uint32_t* a, const uint32_t* b) {
    asm volatile("mma.sync.aligned.m16n8k8.row.col.f32.tf32.tf32.f32 "
        "{%0,%1,%2,%3}, {%4,%5,%6,%7}, {%8,%9}, {%0,%1,%2,%3};"
        : "+f"(c[0]), "+f"(c[1]), "+f"(c[2]), "+f"(c[3])
        : "r"(a[0]), "r"(a[1]), "r"(a[2]), "r"(a[3]), "r"(b[0]), "r"(b[1]));
}

// ------------------------------------------------------------------
// K1: proj_x
// ------------------------------------------------------------------
__global__ void __launch_bounds__(256) k_proj(const float* __restrict__ x,
                                              const float* __restrict__ W0,
                                              const float* __restrict__ b0,
                                              const float* __restrict__ W1,
                                              const float* __restrict__ b1) {
    __shared__ float xs[8][64];
    __shared__ float hs[8][512];
    int b  = blockIdx.x >> 4;
    int t0 = (blockIdx.x & 15) * 8;
    int tid = threadIdx.x;

    for (int i = tid; i < 8 * 64; i += 256) {
        int tt = i >> 6, k = i & 63;
        xs[tt][k] = x[(b * (O_ + L_) + t0 + tt) * S_ + k];
    }
    __syncthreads();

    #pragma unroll
    for (int jj = 0; jj < 2; jj++) {
        int j = tid + jj * 256;
        float acc[8];
        float bj = b0[j];
        #pragma unroll
        for (int tt = 0; tt < 8; tt++) acc[tt] = bj;
        for (int k = 0; k < 64; k++) {
            float w = W0[j * 64 + k];
            #pragma unroll
            for (int tt = 0; tt < 8; tt++) acc[tt] += w * xs[tt][k];
        }
        #pragma unroll
        for (int tt = 0; tt < 8; tt++) hs[tt][j] = fmaxf(acc[tt], 0.0f);
    }
    __syncthreads();

    int n = tid;
    float acc2[8];
    float bn = b1[n];
    #pragma unroll
    for (int tt = 0; tt < 8; tt++) acc2[tt] = bn;
    for (int j = 0; j < 512; j++) {
        float w = W1[n * 512 + j];
        #pragma unroll
        for (int tt = 0; tt < 8; tt++) acc2[tt] += w * hs[tt][j];
    }
    #pragma unroll
    for (int tt = 0; tt < 8; tt++) g_p[(b * L_ + t0 + tt) * N_ + n] = acc2[tt];
}

// ------------------------------------------------------------------
// K2: silu -> depthwise conv (K=4) -> silu.
// ------------------------------------------------------------------
__global__ void k_conv(const float* __restrict__ u,
                       const float* __restrict__ cw,
                       const float* __restrict__ cb) {
    int tok = blockIdx.x;
    int b = tok >> 7, l = tok & 127;
    int c = threadIdx.x;   // 0..287
    float acc = cb[c];
    #pragma unroll
    for (int k = 0; k < KC; k++) {
        int i = l - 1 + k;
        if (i >= 0 && i <= 126) {
            float v = (c < 256) ? g_p[((b << 7) + i) * N_ + c]
                                : u[(b * 256 + i) * U_ + (c - 256)];
            acc += cw[c * 4 + k] * siluf(v);
        }
    }
    g_old[tok * CDIM + c] = siluf(acc);
}

// ------------------------------------------------------------------
// K3: TF32 tensor-core GEMM via mma.sync.
// g_gen[m][n] = bg[n] + sum_k g_old[m][k] * Wg[n][k]
// BM=128, BN=128, BK=32. 8 warps; warp tile 64x32 (4x4 m16n8k8 frags).
// SMEM k-major [k][row], stride 137 -> conflict-free STS transpose.
// Register-staged prefetch of the next K-tile overlaps LDG with MMA.
// ------------------------------------------------------------------
#define SMST 137
__global__ void __launch_bounds__(256) k_gemm(const float* __restrict__ Wg,
                                              const float* __restrict__ bg) {
    __shared__ uint32_t As[32 * SMST];
    __shared__ uint32_t Bs[32 * SMST];
    int m0 = blockIdx.y * 128;
    int n0 = blockIdx.x * 128;
    int tid = threadIdx.x;
    int wid = tid >> 5, lane = tid & 31;
    int wm = wid >> 2, wn = wid & 3;           // 2 x 4 warp grid
    int group = lane >> 2, tid4 = lane & 3;
    int mBase = wm * 64, nBase = wn * 32;

    float acc[4][4][4];
    #pragma unroll
    for (int i = 0; i < 4; i++)
        #pragma unroll
        for (int j = 0; j < 4; j++)
            #pragma unroll
            for (int q = 0; q < 4; q++) acc[i][j][q] = 0.0f;

    float4 ra[4], rb[4];
    int ldRow = tid >> 3;            // 0..31 base row pattern per p
    int ldC4  = (tid & 7) * 4;

    // prefetch tile 0
    #pragma unroll
    for (int p = 0; p < 4; p++) {
        int row = ldRow + p * 32;
        ra[p] = *reinterpret_cast<const float4*>(&g_old[(m0 + row) * KDIM + ldC4]);
        rb[p] = (n0 + row < DOUT)
              ? *reinterpret_cast<const float4*>(&Wg[(size_t)(n0 + row) * KDIM + ldC4])
              : make_float4(0.f, 0.f, 0.f, 0.f);
    }

    #pragma unroll 1
    for (int it = 0; it < 9; it++) {
        // stage registers -> smem transposed (tf32-rounded)
        #pragma unroll
        for (int p = 0; p < 4; p++) {
            int row = ldRow + p * 32;
            As[(ldC4 + 0) * SMST + row] = tf32r(ra[p].x);
            As[(ldC4 + 1) * SMST + row] = tf32r(ra[p].y);
            As[(ldC4 + 2) * SMST + row] = tf32r(ra[p].z);
            As[(ldC4 + 3) * SMST + row] = tf32r(ra[p].w);
            Bs[(ldC4 + 0) * SMST + row] = tf32r(rb[p].x);
            Bs[(ldC4 + 1) * SMST + row] = tf32r(rb[p].y);
            Bs[(ldC4 + 2) * SMST + row] = tf32r(rb[p].z);
            Bs[(ldC4 + 3) * SMST + row] = tf32r(rb[p].w);
        }
        __syncthreads();

        // prefetch next tile
        if (it < 8) {
            int k0 = (it + 1) * 32;
            #pragma unroll
            for (int p = 0; p < 4; p++) {
                int row = ldRow + p * 32;
                ra[p] = *reinterpret_cast<const float4*>(&g_old[(m0 + row) * KDIM + k0 + ldC4]);
                rb[p] = (n0 + row < DOUT)
                      ? *reinterpret_cast<const float4*>(&Wg[(size_t)(n0 + row) * KDIM + k0 + ldC4])
                      : make_float4(0.f, 0.f, 0.f, 0.f);
            }
        }

        #pragma unroll
        for (int ks = 0; ks < 4; ks++) {
            int krow = ks * 8 + tid4;
            const uint32_t* A0 = &As[krow * SMST];
            const uint32_t* A1 = &As[(krow + 4) * SMST];
            const uint32_t* B0 = &Bs[krow * SMST];
            const uint32_t* B1 = &Bs[(krow + 4) * SMST];
            uint32_t af[4][4], bf[4][2];
            #pragma unroll
            for (int mt = 0; mt < 4; mt++) {
                int m = mBase + mt * 16 + group;
                af[mt][0] = A0[m];     af[mt][1] = A0[m + 8];
                af[mt][2] = A1[m];     af[mt][3] = A1[m + 8];
            }
            #pragma unroll
            for (int nt = 0; nt < 4; nt++) {
                int n = nBase + nt * 8 + group;
                bf[nt][0] = B0[n];     bf[nt][1] = B1[n];
            }
            #pragma unroll
            for (int mt = 0; mt < 4; mt++)
                #pragma unroll
                for (int nt = 0; nt < 4; nt++)
                    mma8(acc[mt][nt], af[mt], bf[nt]);
        }
        __syncthreads();
    }

    // epilogue: write fragments directly, bias fused, float2 stores
    #pragma unroll
    for (int mt = 0; mt < 4; mt++) {
        int r0 = m0 + mBase + mt * 16 + group;
        #pragma unroll
        for (int nt = 0; nt < 4; nt++) {
            int c = n0 + nBase + nt * 8 + tid4 * 2;
            if (c < DOUT) {
                float2 bgv = *reinterpret_cast<const float2*>(&bg[c]);
                float2 v0 = make_float2(acc[mt][nt][0] + bgv.x, acc[mt][nt][1] + bgv.y);
                float2 v1 = make_float2(acc[mt][nt][2] + bgv.x, acc[mt][nt][3] + bgv.y);
                *reinterpret_cast<float2*>(&g_gen[(size_t)r0 * DOUT + c]) = v0;
                *reinterpret_cast<float2*>(&g_gen[(size_t)(r0 + 8) * DOUT + c]) = v1;
            }
        }
    }
}

// ------------------------------------------------------------------
// K4: delta path via warp-shuffle reduction.
// ------------------------------------------------------------------
__global__ void __launch_bounds__(128) k_delta(const float* __restrict__ A,
                                               const float* __restrict__ Wdt,
                                               const float* __restrict__ bdt) {
    int tok = blockIdx.x * 4 + (threadIdx.x >> 5);
    int lane = threadIdx.x & 31;
    const float* gp = &g_gen[(size_t)tok * DOUT];
    float dlo = gp[lane];
    float dhi = gp[32 + lane];

    float res[8];
    #pragma unroll
    for (int g = 0; g < 8; g++) {
        float myres = 0.0f;
        #pragma unroll
        for (int j = 0; j < 32; j++) {
            int n = g * 32 + j;
            float p = dlo * Wdt[n * 64 + lane] + dhi * Wdt[n * 64 + 32 + lane];
            #pragma unroll
            for (int o = 16; o > 0; o >>= 1)
                p += __shfl_xor_sync(0xffffffffu, p, o);
            if (lane == j) myres = p;
        }
        res[g] = myres;
    }
    #pragma unroll
    for (int g = 0; g < 8; g++) {
        int n = g * 32 + lane;
        float acc = res[g] + bdt[n];
        float sp = fmaxf(acc, 0.0f) + log1pf(expf(-fabsf(acc)));
        float a = A[n];
        float an = (a > 0.0f) ? -a : -expm1f(a);
        float dA = expf(sp * an);
        g_dA[tok * N_ + n] = dA;
        g_coeff[tok * N_ + n] = (dA - 1.0f) / an;
    }
}

// ------------------------------------------------------------------
// K5: Bu[tok][n] = coeff * sum_u Bm[tok][n][u] * u0[tok][u]
// ------------------------------------------------------------------
__global__ void __launch_bounds__(256) k_bu(const float* __restrict__ u) {
    __shared__ float sB[256 * 33];
    __shared__ float us[32];
    int tok = blockIdx.x;
    int b = tok >> 7, t = tok & 127;
    int tid = threadIdx.x;
    if (tid < 32) us[tid] = u[(b * 256 + 127 + t) * U_ + tid];
    const float4* src = reinterpret_cast<const float4*>(&g_gen[(size_t)tok * DOUT + DEL]);
    #pragma unroll
    for (int q = 0; q < 8; q++) {
        int e4 = tid + q * 256;
        float4 v = src[e4];
        int n  = e4 >> 3;
        int u0 = (e4 & 7) * 4;
        float* dst = &sB[n * 33 + u0];
        dst[0] = v.x; dst[1] = v.y; dst[2] = v.z; dst[3] = v.w;
    }
    __syncthreads();
    float acc = 0.0f;
    #pragma unroll
    for (int uu = 0; uu < 32; uu++) acc += sB[tid * 33 + uu] * us[uu];
    g_Bu[tok * N_ + tid] = g_coeff[tok * N_ + tid] * acc;
}

// ------------------------------------------------------------------
// K6: sequential scan, unroll-8 batched loads.
// ------------------------------------------------------------------
__global__ void k_scan() {
    int b = blockIdx.x;
    int n = threadIdx.x;
    float z = g_p[((b << 7) + 127) * N_ + n];
    for (int t0 = 0; t0 < L_; t0 += 8) {
        float da[8], bu[8];
        #pragma unroll
        for (int q = 0; q < 8; q++) {
            int idx = ((b << 7) + t0 + q) * N_ + n;
            da[q] = g_dA[idx];
            bu[q] = g_Bu[idx];
        }
        #pragma unroll
        for (int q = 0; q < 8; q++) {
            z = z * da[q] + bu[q];
            g_z[((b << 7) + t0 + q) * N_ + n] = z;
        }
    }
}

// ------------------------------------------------------------------
// K7: y[b,t,s] = sum_n Cm[tok][n][s] * z[tok][n]; sq-err partials.
// ------------------------------------------------------------------
__global__ void k_y(const float* __restrict__ x, float* __restrict__ out) {
    __shared__ float zs[256];
    __shared__ float red[2];
    int tok = blockIdx.x;
    int b = tok >> 7, t = tok & 127;
    int s = threadIdx.x;   // 0..63
    for (int i = s; i < 256; i += 64) zs[i] = g_z[tok * N_ + i];
    __syncthreads();
    const float* gp = &g_gen[(size_t)tok * DOUT + DEL + N_ * U_ + s];
    float acc = 0.0f;
    #pragma unroll 8
    for (int n = 0; n < 256; n++) acc += gp[n * 64] * zs[n];
    out[1 + ((t << 4) + b) * S_ + s] = acc;
    float diff = acc - x[(b * 256 + 128 + t) * S_ + s];
    float v = diff * diff;
    #pragma unroll
    for (int o = 16; o > 0; o >>= 1) v += __shfl_down_sync(0xffffffffu, v, o);
    if ((s & 31) == 0) red[s >> 5] = v;
    __syncthreads();
    if (s == 0) g_part[tok] = red[0] + red[1];
}

// ------------------------------------------------------------------
// K8: loss reduction.
// ------------------------------------------------------------------
__global__ void k_loss(float* __restrict__ out) {
    __shared__ float red[256];
    float v = 0.0f;
    for (int i = threadIdx.x; i < TOK; i += 256) v += g_part[i];
    red[threadIdx.x] = v;
    __syncthreads();
    for (int st = 128; st > 0; st >>= 1) {
        if (threadIdx.x < st) red[threadIdx.x] += red[threadIdx.x + st];
        __syncthreads();
    }
    if (threadIdx.x == 0) out[0] = red[0] / (float)(B_ * S_ * L_);
}

// ------------------------------------------------------------------
extern "C" void kernel_launch(void* const* d_in, const int* in_sizes, int n_in,
                              void* d_out, int out_size) {
    const float* x   = (const float*)d_in[0];
    const float* u   = (const float*)d_in[1];
    const float* A   = (const float*)d_in[2];
    const float* W0  = (const float*)d_in[3];
    const float* b0  = (const float*)d_in[4];
    const float* W1  = (const float*)d_in[5];
    const float* b1  = (const float*)d_in[6];
    const float* cw  = (const float*)d_in[7];
    const float* cb  = (const float*)d_in[8];
    const float* Wg  = (const float*)d_in[9];
    const float* bg  = (const float*)d_in[10];
    const float* Wdt = (const float*)d_in[11];
    const float* bdt = (const float*)d_in[12];
    float* out = (float*)d_out;

    k_proj<<<256, 256>>>(x, W0, b0, W1, b1);
    k_conv<<<TOK, CDIM>>>(u, cw, cb);
    dim3 gg((DOUT + 127) / 128, TOK / 128);   // (193, 16)
    k_gemm<<<gg, 256>>>(Wg, bg);
    k_delta<<<TOK / 4, 128>>>(A, Wdt, bdt);
    k_bu<<<TOK, 256>>>(u);
    k_scan<<<B_, N_>>>();
    k_y<<<TOK, S_>>>(x, out);
    k_loss<<<1, 256>>>(out);
}

// round 7
// speedup vs baseline: 2.2747x; 1.0128x over previous
#include <cuda_runtime.h>
#include <math.h>
#include <stdint.h>

// ---- problem constants ----
#define B_   16
#define L_   128
#define O_   128
#define N_   256
#define S_   64
#define U_   32
#define DEL  64
#define HID  512
#define KC   4
#define CDIM 288           // N_ + U_
#define TOK  2048          // B_ * L_
#define KDIM 288
#define NBM  8192          // N_*U_  (Bm cols)
#define NCM  16384         // N_*S_  (Cm cols)

// ---- scratch (device globals) ----
__device__ float g_p[TOK * N_];
__device__ float g_old[TOK * CDIM];
__device__ float g_wc[N_ * KDIM];      // combined delta weights
__device__ float g_bc[N_];             // combined delta bias
__device__ float g_dpre[TOK * N_];     // raw delta projection
__device__ float g_dA[TOK * N_];
__device__ float g_coeff[TOK * N_];
__device__ float g_buraw[TOK * N_];
__device__ float g_z[TOK * N_];
__device__ float g_y[TOK * S_];
__device__ float g_part[TOK];

__device__ __forceinline__ float siluf(float v) { return v / (1.0f + expf(-v)); }

__device__ __forceinline__ uint32_t tf32r(float f) {
    uint32_t r; asm("cvt.rna.tf32.f32 %0, %1;" : "=r"(r) : "f"(f)); return r;
}
__device__ __forceinline__ void mma8(float* c, const uint32_t* a, const uint32_t* b) {
    asm volatile("mma.sync.aligned.m16n8k8.row.col.f32.tf32.tf32.f32 "
        "{%0,%1,%2,%3}, {%4,%5,%6,%7}, {%8,%9}, {%0,%1,%2,%3};"
        : "+f"(c[0]), "+f"(c[1]), "+f"(c[2]), "+f"(c[3])
        : "r"(a[0]), "r"(a[1]), "r"(a[2]), "r"(a[3]), "r"(b[0]), "r"(b[1]));
}

// ------------------------------------------------------------------
// Shared tf32 GEMM mainloop: 128x128 tile, K=288 (9 x BK=32).
// acc fragment layout (validated in R6):
//   rows r0 = m0 + (wid>>2)*64 + mt*16 + (lane>>2), r0+8
//   cols c  = (wid&3)*32 + nt*8 + (lane&3)*2, c+1
// ------------------------------------------------------------------
#define SMST 137
__device__ __forceinline__ void gemm_tile(uint32_t* As, uint32_t* Bs,
                                          const float* __restrict__ Aptr,
                                          const float* __restrict__ Bptr,
                                          int tid, float acc[4][4][4]) {
    int lane = tid & 31;
    int wid = tid >> 5;
    int wm = wid >> 2, wn = wid & 3;
    int group = lane >> 2, tid4 = lane & 3;
    int mBase = wm * 64, nBase = wn * 32;
    int ldRow = tid >> 3;
    int ldC4 = (tid & 7) * 4;

    #pragma unroll
    for (int i = 0; i < 4; i++)
        #pragma unroll
        for (int j = 0; j < 4; j++)
            #pragma unroll
            for (int q = 0; q < 4; q++) acc[i][j][q] = 0.0f;

    float4 ra[4], rb[4];
    #pragma unroll
    for (int p = 0; p < 4; p++) {
        int row = ldRow + p * 32;
        ra[p] = *reinterpret_cast<const float4*>(&Aptr[(size_t)row * KDIM + ldC4]);
        rb[p] = *reinterpret_cast<const float4*>(&Bptr[(size_t)row * KDIM + ldC4]);
    }

    #pragma unroll 1
    for (int it = 0; it < 9; it++) {
        #pragma unroll
        for (int p = 0; p < 4; p++) {
            int row = ldRow + p * 32;
            As[(ldC4 + 0) * SMST + row] = tf32r(ra[p].x);
            As[(ldC4 + 1) * SMST + row] = tf32r(ra[p].y);
            As[(ldC4 + 2) * SMST + row] = tf32r(ra[p].z);
            As[(ldC4 + 3) * SMST + row] = tf32r(ra[p].w);
            Bs[(ldC4 + 0) * SMST + row] = tf32r(rb[p].x);
            Bs[(ldC4 + 1) * SMST + row] = tf32r(rb[p].y);
            Bs[(ldC4 + 2) * SMST + row] = tf32r(rb[p].z);
            Bs[(ldC4 + 3) * SMST + row] = tf32r(rb[p].w);
        }
        __syncthreads();

        if (it < 8) {
            int k0 = (it + 1) * 32;
            #pragma unroll
            for (int p = 0; p < 4; p++) {
                int row = ldRow + p * 32;
                ra[p] = *reinterpret_cast<const float4*>(&Aptr[(size_t)row * KDIM + k0 + ldC4]);
                rb[p] = *reinterpret_cast<const float4*>(&Bptr[(size_t)row * KDIM + k0 + ldC4]);
            }
        }

        #pragma unroll
        for (int ks = 0; ks < 4; ks++) {
            int krow = ks * 8 + tid4;
            const uint32_t* A0 = &As[krow * SMST];
            const uint32_t* A1 = &As[(krow + 4) * SMST];
            const uint32_t* B0 = &Bs[krow * SMST];
            const uint32_t* B1 = &Bs[(krow + 4) * SMST];
            uint32_t af[4][4], bf[4][2];
            #pragma unroll
            for (int mt = 0; mt < 4; mt++) {
                int m = mBase + mt * 16 + group;
                af[mt][0] = A0[m]; af[mt][1] = A0[m + 8];
                af[mt][2] = A1[m]; af[mt][3] = A1[m + 8];
            }
            #pragma unroll
            for (int nt = 0; nt < 4; nt++) {
                int n = nBase + nt * 8 + group;
                bf[nt][0] = B0[n]; bf[nt][1] = B1[n];
            }
            #pragma unroll
            for (int mt = 0; mt < 4; mt++)
                #pragma unroll
                for (int nt = 0; nt < 4; nt++)
                    mma8(acc[mt][nt], af[mt], bf[nt]);
        }
        __syncthreads();
    }
}

// ------------------------------------------------------------------
// K1: proj_x
// ------------------------------------------------------------------
__global__ void __launch_bounds__(256) k_proj(const float* __restrict__ x,
                                              const float* __restrict__ W0,
                                              const float* __restrict__ b0,
                                              const float* __restrict__ W1,
                                              const float* __restrict__ b1) {
    __shared__ float xs[8][64];
    __shared__ float hs[8][512];
    int b  = blockIdx.x >> 4;
    int t0 = (blockIdx.x & 15) * 8;
    int tid = threadIdx.x;

    for (int i = tid; i < 8 * 64; i += 256) {
        int tt = i >> 6, k = i & 63;
        xs[tt][k] = x[(b * (O_ + L_) + t0 + tt) * S_ + k];
    }
    __syncthreads();

    #pragma unroll
    for (int jj = 0; jj < 2; jj++) {
        int j = tid + jj * 256;
        float acc[8];
        float bj = b0[j];
        #pragma unroll
        for (int tt = 0; tt < 8; tt++) acc[tt] = bj;
        for (int k = 0; k < 64; k++) {
            float w = W0[j * 64 + k];
            #pragma unroll
            for (int tt = 0; tt < 8; tt++) acc[tt] += w * xs[tt][k];
        }
        #pragma unroll
        for (int tt = 0; tt < 8; tt++) hs[tt][j] = fmaxf(acc[tt], 0.0f);
    }
    __syncthreads();

    int n = tid;
    float acc2[8];
    float bn = b1[n];
    #pragma unroll
    for (int tt = 0; tt < 8; tt++) acc2[tt] = bn;
    for (int j = 0; j < 512; j++) {
        float w = W1[n * 512 + j];
        #pragma unroll
        for (int tt = 0; tt < 8; tt++) acc2[tt] += w * hs[tt][j];
    }
    #pragma unroll
    for (int tt = 0; tt < 8; tt++) g_p[(b * L_ + t0 + tt) * N_ + n] = acc2[tt];
}

// ------------------------------------------------------------------
// K2: silu -> depthwise conv -> silu.
// ------------------------------------------------------------------
__global__ void k_conv(const float* __restrict__ u,
                       const float* __restrict__ cw,
                       const float* __restrict__ cb) {
    int tok = blockIdx.x;
    int b = tok >> 7, l = tok & 127;
    int c = threadIdx.x;   // 0..287
    float acc = cb[c];
    #pragma unroll
    for (int k = 0; k < KC; k++) {
        int i = l - 1 + k;
        if (i >= 0 && i <= 126) {
            float v = (c < 256) ? g_p[((b << 7) + i) * N_ + c]
                                : u[(b * 256 + i) * U_ + (c - 256)];
            acc += cw[c * 4 + k] * siluf(v);
        }
    }
    g_old[tok * CDIM + c] = siluf(acc);
}

// ------------------------------------------------------------------
// K3: combined delta weights Wc = Wdt @ Wg[0:64], bc = Wdt@bg[0:64]+bdt.
// Also zeros g_y for the atomic y accumulation.
// ------------------------------------------------------------------
__global__ void k_wcomb(const float* __restrict__ Wg, const float* __restrict__ bg,
                        const float* __restrict__ Wdt, const float* __restrict__ bdt) {
    __shared__ float sw[64];
    int n = blockIdx.x;       // 0..255
    int tid = threadIdx.x;    // 0..287
    if (tid < 64) sw[tid] = Wdt[n * 64 + tid];
    __syncthreads();
    float acc = 0.0f;
    #pragma unroll 8
    for (int d = 0; d < 64; d++) acc += sw[d] * Wg[d * KDIM + tid];
    g_wc[n * KDIM + tid] = acc;
    if (tid == 0) {
        float s = bdt[n];
        for (int d = 0; d < 64; d++) s += sw[d] * bg[d];
        g_bc[n] = s;
    }
    for (int i = blockIdx.x * blockDim.x + tid; i < TOK * S_; i += gridDim.x * blockDim.x)
        g_y[i] = 0.0f;
}

// ------------------------------------------------------------------
// K4: delta GEMM: g_dpre = old @ Wc^T  (M=2048, N=256, K=288)
// ------------------------------------------------------------------
__global__ void __launch_bounds__(256) k_gemm_delta() {
    __shared__ uint32_t As[32 * SMST];
    __shared__ uint32_t Bs[32 * SMST];
    int m0 = blockIdx.y * 128;
    int n0 = blockIdx.x * 128;
    int tid = threadIdx.x;
    int lane = tid & 31, wid = tid >> 5;
    int wm = wid >> 2, wn = wid & 3;
    int group = lane >> 2, tid4 = lane & 3;
    float acc[4][4][4];
    gemm_tile(As, Bs, &g_old[(size_t)m0 * KDIM], &g_wc[(size_t)n0 * KDIM], tid, acc);

    #pragma unroll
    for (int mt = 0; mt < 4; mt++) {
        int r0 = m0 + wm * 64 + mt * 16 + group;
        #pragma unroll
        for (int nt = 0; nt < 4; nt++) {
            int c = n0 + wn * 32 + nt * 8 + tid4 * 2;
            *reinterpret_cast<float2*>(&g_dpre[r0 * N_ + c]) =
                make_float2(acc[mt][nt][0], acc[mt][nt][1]);
            *reinterpret_cast<float2*>(&g_dpre[(r0 + 8) * N_ + c]) =
                make_float2(acc[mt][nt][2], acc[mt][nt][3]);
        }
    }
}

// ------------------------------------------------------------------
// K5: delta transform (full chip): softplus -> dA, coeff.
// ------------------------------------------------------------------
__global__ void k_dtrans(const float* __restrict__ A) {
    int idx0 = blockIdx.x * blockDim.x + threadIdx.x;
    for (int idx = idx0; idx < TOK * N_; idx += gridDim.x * blockDim.x) {
        int n = idx & 255;
        float acc = g_dpre[idx] + g_bc[n];
        float sp = fmaxf(acc, 0.0f) + log1pf(expf(-fabsf(acc)));
        float a = A[n];
        float an = (a > 0.0f) ? -a : -expm1f(a);
        float dA = expf(sp * an);
        g_dA[idx] = dA;
        g_coeff[idx] = (dA - 1.0f) / an;
    }
}

// ------------------------------------------------------------------
// K6: Bm GEMM (Wg rows 64..8255) with fused Bu epilogue.
// Warp wn owns cols [wn*32, wn*32+32) = all 32 u of n = bx*4+wn.
// bu_raw[tok][n] = sum_u (Bm+bg)*u0 via in-register + shfl reduction.
// ------------------------------------------------------------------
__global__ void __launch_bounds__(256) k_gemm_bu(const float* __restrict__ Wg,
                                                 const float* __restrict__ bg,
                                                 const float* __restrict__ u) {
    __shared__ uint32_t As[32 * SMST];
    __shared__ uint32_t Bs[32 * SMST];
    int m0 = blockIdx.y * 128;
    int n0 = blockIdx.x * 128;     // local col in [0, 8192)
    int tid = threadIdx.x;
    int lane = tid & 31, wid = tid >> 5;
    int wm = wid >> 2, wn = wid & 3;
    int group = lane >> 2, tid4 = lane & 3;
    float acc[4][4][4];
    gemm_tile(As, Bs, &g_old[(size_t)m0 * KDIM], &Wg[(size_t)(DEL + n0) * KDIM], tid, acc);

    int nb = blockIdx.x * 4 + wn;                 // global n for this warp
    const float* bgp = &bg[DEL + n0 + wn * 32];   // bias for this warp's 32 u-cols

    #pragma unroll
    for (int mt = 0; mt < 4; mt++) {
        int r0 = m0 + wm * 64 + mt * 16 + group;
        int r1 = r0 + 8;
        const float* u0p = &u[((r0 >> 7) * 256 + 127 + (r0 & 127)) * U_];
        const float* u1p = &u[((r1 >> 7) * 256 + 127 + (r1 & 127)) * U_];
        float s0 = 0.0f, s1 = 0.0f;
        #pragma unroll
        for (int nt = 0; nt < 4; nt++) {
            int uu = nt * 8 + tid4 * 2;
            float bg0 = bgp[uu], bg1 = bgp[uu + 1];
            s0 += (acc[mt][nt][0] + bg0) * u0p[uu] + (acc[mt][nt][1] + bg1) * u0p[uu + 1];
            s1 += (acc[mt][nt][2] + bg0) * u1p[uu] + (acc[mt][nt][3] + bg1) * u1p[uu + 1];
        }
        s0 += __shfl_xor_sync(0xffffffffu, s0, 1);
        s0 += __shfl_xor_sync(0xffffffffu, s0, 2);
        s1 += __shfl_xor_sync(0xffffffffu, s1, 1);
        s1 += __shfl_xor_sync(0xffffffffu, s1, 2);
        if (tid4 == 0) {
            g_buraw[r0 * N_ + nb] = s0;
            g_buraw[r1 * N_ + nb] = s1;
        }
    }
}

// ------------------------------------------------------------------
// K7: sequential scan: z = z*dA + coeff*bu_raw.
// ------------------------------------------------------------------
__global__ void k_scan() {
    int b = blockIdx.x;
    int n = threadIdx.x;
    float z = g_p[((b << 7) + 127) * N_ + n];
    for (int t0 = 0; t0 < L_; t0 += 8) {
        float da[8], bu[8], cf[8];
        #pragma unroll
        for (int q = 0; q < 8; q++) {
            int idx = ((b << 7) + t0 + q) * N_ + n;
            da[q] = g_dA[idx];
            bu[q] = g_buraw[idx];
            cf[q] = g_coeff[idx];
        }
        #pragma unroll
        for (int q = 0; q < 8; q++) {
            z = z * da[q] + cf[q] * bu[q];
            g_z[((b << 7) + t0 + q) * N_ + n] = z;
        }
    }
}

// ------------------------------------------------------------------
// K8: Cm GEMM (Wg rows 8256..24639) with fused y epilogue.
// Block loops 4 n-tiles (512 cols); fragment (row,s) positions are fixed
// across tiles, so y accumulates in registers; one atomicAdd pass at end.
// ------------------------------------------------------------------
__global__ void __launch_bounds__(256, 1) k_gemm_y(const float* __restrict__ Wg,
                                                   const float* __restrict__ bg) {
    __shared__ uint32_t As[32 * SMST];
    __shared__ uint32_t Bs[32 * SMST];
    int m0 = blockIdx.y * 128;
    int cb0 = blockIdx.x * 512;    // local Cm col base in [0, 16384)
    int tid = threadIdx.x;
    int lane = tid & 31, wid = tid >> 5;
    int wm = wid >> 2, wn = wid & 3;
    int group = lane >> 2, tid4 = lane & 3;

    float yacc[4][4][4];
    #pragma unroll
    for (int i = 0; i < 4; i++)
        #pragma unroll
        for (int j = 0; j < 4; j++)
            #pragma unroll
            for (int q = 0; q < 4; q++) yacc[i][j][q] = 0.0f;

    #pragma unroll 1
    for (int tt = 0; tt < 4; tt++) {
        int cb = cb0 + tt * 128;
        float acc[4][4][4];
        gemm_tile(As, Bs, &g_old[(size_t)m0 * KDIM],
                  &Wg[(size_t)(DEL + NBM + cb) * KDIM], tid, acc);
        int nidx = (cb >> 6) + (wn >> 1);              // global n for this thread
        const float* bgp = &bg[DEL + NBM + cb + wn * 32];
        #pragma unroll
        for (int mt = 0; mt < 4; mt++) {
            int r0 = m0 + wm * 64 + mt * 16 + group;
            float z0 = g_z[r0 * N_ + nidx];
            float z1 = g_z[(r0 + 8) * N_ + nidx];
            #pragma unroll
            for (int nt = 0; nt < 4; nt++) {
                int cc = nt * 8 + tid4 * 2;
                float bg0 = bgp[cc], bg1 = bgp[cc + 1];
                yacc[mt][nt][0] += (acc[mt][nt][0] + bg0) * z0;
                yacc[mt][nt][1] += (acc[mt][nt][1] + bg1) * z0;
                yacc[mt][nt][2] += (acc[mt][nt][2] + bg0) * z1;
                yacc[mt][nt][3] += (acc[mt][nt][3] + bg1) * z1;
            }
        }
    }

    // atomic accumulation into g_y[tok][s];  s = col & 63 (fixed across tiles)
    #pragma unroll
    for (int mt = 0; mt < 4; mt++) {
        int r0 = m0 + wm * 64 + mt * 16 + group;
        #pragma unroll
        for (int nt = 0; nt < 4; nt++) {
            int s = (wn * 32 + nt * 8 + tid4 * 2) & 63;
            atomicAdd(&g_y[r0 * S_ + s],       yacc[mt][nt][0]);
            atomicAdd(&g_y[r0 * S_ + s + 1],   yacc[mt][nt][1]);
            atomicAdd(&g_y[(r0 + 8) * S_ + s],     yacc[mt][nt][2]);
            atomicAdd(&g_y[(r0 + 8) * S_ + s + 1], yacc[mt][nt][3]);
        }
    }
}

// ------------------------------------------------------------------
// K9: y finalize: write ys in (t,b,s) order + per-token mse partial.
// ------------------------------------------------------------------
__global__ void k_yfin(const float* __restrict__ x, float* __restrict__ out) {
    __shared__ float red[2];
    int tok = blockIdx.x;
    int b = tok >> 7, t = tok & 127;
    int s = threadIdx.x;   // 0..63
    float yv = g_y[tok * S_ + s];
    out[1 + ((t << 4) + b) * S_ + s] = yv;
    float diff = yv - x[(b * 256 + 128 + t) * S_ + s];
    float v = diff * diff;
    #pragma unroll
    for (int o = 16; o > 0; o >>= 1) v += __shfl_down_sync(0xffffffffu, v, o);
    if ((s & 31) == 0) red[s >> 5] = v;
    __syncthreads();
    if (s == 0) g_part[tok] = red[0] + red[1];
}

// ------------------------------------------------------------------
// K10: loss reduction.
// ------------------------------------------------------------------
__global__ void k_loss(float* __restrict__ out) {
    __shared__ float red[256];
    float v = 0.0f;
    for (int i = threadIdx.x; i < TOK; i += 256) v += g_part[i];
    red[threadIdx.x] = v;
    __syncthreads();
    for (int st = 128; st > 0; st >>= 1) {
        if (threadIdx.x < st) red[threadIdx.x] += red[threadIdx.x + st];
        __syncthreads();
    }
    if (threadIdx.x == 0) out[0] = red[0] / (float)(B_ * S_ * L_);
}

// ------------------------------------------------------------------
extern "C" void kernel_launch(void* const* d_in, const int* in_sizes, int n_in,
                              void* d_out, int out_size) {
    const float* x   = (const float*)d_in[0];
    const float* u   = (const float*)d_in[1];
    const float* A   = (const float*)d_in[2];
    const float* W0  = (const float*)d_in[3];
    const float* b0  = (const float*)d_in[4];
    const float* W1  = (const float*)d_in[5];
    const float* b1  = (const float*)d_in[6];
    const float* cw  = (const float*)d_in[7];
    const float* cb  = (const float*)d_in[8];
    const float* Wg  = (const float*)d_in[9];
    const float* bg  = (const float*)d_in[10];
    const float* Wdt = (const float*)d_in[11];
    const float* bdt = (const float*)d_in[12];
    float* out = (float*)d_out;

    k_proj<<<256, 256>>>(x, W0, b0, W1, b1);
    k_conv<<<TOK, CDIM>>>(u, cw, cb);
    k_wcomb<<<N_, CDIM>>>(Wg, bg, Wdt, bdt);
    k_gemm_delta<<<dim3(2, 16), 256>>>();
    k_dtrans<<<512, 256>>>(A);
    k_gemm_bu<<<dim3(NBM / 128, 16), 256>>>(Wg, bg, u);
    k_scan<<<B_, N_>>>();
    k_gemm_y<<<dim3(NCM / 512, 16), 256>>>(Wg, bg);
    k_yfin<<<TOK, S_>>>(x, out);
    k_loss<<<1, 256>>>(out);
}

// round 8
// speedup vs baseline: 2.7384x; 1.2039x over previous
#include <cuda_runtime.h>
#include <math.h>
#include <stdint.h>

// ---- problem constants ----
#define B_   16
#define L_   128
#define O_   128
#define N_   256
#define S_   64
#define U_   32
#define DEL  64
#define HID  512
#define KC   4
#define CDIM 288           // N_ + U_
#define TOK  2048          // B_ * L_
#define KDIM 288
#define NBM  8192          // N_*U_  (Bm cols)
#define NCM  16384         // N_*S_  (Cm cols)
#define WROWS (NBM + NCM)  // 24576 rounded Wg rows (starting at DEL)

// ---- scratch (device globals) ----
__device__ __align__(16) float g_p[TOK * N_];
__device__ __align__(16) float g_old[TOK * CDIM];
__device__ __align__(16) float g_wgt[(size_t)WROWS * KDIM];  // tf32-rounded Wg[64:]
__device__ __align__(16) float g_wc[N_ * KDIM];
__device__ float g_bc[N_];
__device__ __align__(16) float g_dpre[TOK * N_];
__device__ float g_dA[TOK * N_];
__device__ float g_coeff[TOK * N_];
__device__ float g_buraw[TOK * N_];
__device__ float g_z[TOK * N_];
__device__ float g_y[TOK * S_];
__device__ float g_part[TOK];

__device__ __forceinline__ float siluf(float v) { return v / (1.0f + expf(-v)); }

__device__ __forceinline__ float tf32rf(float f) {
    uint32_t r; asm("cvt.rna.tf32.f32 %0, %1;" : "=r"(r) : "f"(f));
    return __uint_as_float(r);
}
__device__ __forceinline__ void mma8(float* c, const uint32_t* a, const uint32_t* b) {
    asm volatile("mma.sync.aligned.m16n8k8.row.col.f32.tf32.tf32.f32 "
        "{%0,%1,%2,%3}, {%4,%5,%6,%7}, {%8,%9}, {%0,%1,%2,%3};"
        : "+f"(c[0]), "+f"(c[1]), "+f"(c[2]), "+f"(c[3])
        : "r"(a[0]), "r"(a[1]), "r"(a[2]), "r"(a[3]), "r"(b[0]), "r"(b[1]));
}
__device__ __forceinline__ void cp16(uint32_t d, const float* s) {
    asm volatile("cp.async.cg.shared.global [%0], [%1], 16;"
                 :: "r"(d), "l"(__cvta_generic_to_global(s)));
}
#define CPCOMMIT() asm volatile("cp.async.commit_group;" ::: "memory")
#define CPWAIT1()  asm volatile("cp.async.wait_group 1;" ::: "memory")
#define CPWAIT0()  asm volatile("cp.async.wait_group 0;" ::: "memory")

// ------------------------------------------------------------------
// Pipelined tf32 GEMM tile: BM=128, BN=64, BK=32, K=288 (9 iters).
// SMEM (uint32 words): A stage s at s*4096 (128x32), B stage s at 8192+s*2048.
// XOR swizzle: word(r,k) = r*32 + (((k>>2) ^ (r&7))<<2) + (k&3)
//  -> 16B cp.async stores and all fragment LDS are bank-conflict-free.
// Fragment map (8 warps, warp tile 32x32):
//  rows r0 = m0 + (wid>>1)*32 + mt*16 + (lane>>2), r0+8   (mt 0..1)
//  cols c  = (wid&1)*32 + nt*8 + (lane&3)*2, c+1           (nt 0..3)
// ------------------------------------------------------------------
__device__ __forceinline__ void pipe_issue(uint32_t sbase, int stage,
                                           const float* __restrict__ Aptr,
                                           const float* __restrict__ Bptr,
                                           int k0, int tid) {
    uint32_t aB = sbase + stage * 4096u * 4u;
    uint32_t bB = sbase + (8192u + stage * 2048u) * 4u;
    #pragma unroll
    for (int p = 0; p < 4; p++) {
        int idx = tid + p * 256;
        int r = idx >> 3, c = idx & 7;
        cp16(aB + (r * 32 + ((c ^ (r & 7)) << 2)) * 4u, Aptr + (size_t)r * KDIM + k0 + c * 4);
    }
    #pragma unroll
    for (int p = 0; p < 2; p++) {
        int idx = tid + p * 256;
        int r = idx >> 3, c = idx & 7;
        cp16(bB + (r * 32 + ((c ^ (r & 7)) << 2)) * 4u, Bptr + (size_t)r * KDIM + k0 + c * 4);
    }
}

__device__ __forceinline__ void gemm_pipe(uint32_t* sm, uint32_t sbase,
                                          const float* __restrict__ Aptr,
                                          const float* __restrict__ Bptr,
                                          int tid, float acc[2][4][4]) {
    int lane = tid & 31, wid = tid >> 5;
    int wm = wid >> 1, wn = wid & 1;
    int group = lane >> 2, tid4 = lane & 3;
    int mBase = wm * 32, nBase = wn * 32;

    #pragma unroll
    for (int i = 0; i < 2; i++)
        #pragma unroll
        for (int j = 0; j < 4; j++)
            #pragma unroll
            for (int q = 0; q < 4; q++) acc[i][j][q] = 0.0f;

    pipe_issue(sbase, 0, Aptr, Bptr, 0, tid);
    CPCOMMIT();

    #pragma unroll 1
    for (int it = 0; it < 9; it++) {
        if (it < 8) {
            pipe_issue(sbase, (it + 1) & 1, Aptr, Bptr, (it + 1) * 32, tid);
            CPCOMMIT();
            CPWAIT1();
        } else {
            CPWAIT0();
        }
        __syncthreads();

        const uint32_t* sA = sm + (it & 1) * 4096;
        const uint32_t* sB = sm + 8192 + (it & 1) * 2048;

        #pragma unroll
        for (int ks = 0; ks < 4; ks++) {
            uint32_t af[2][4], bf[4][2];
            #pragma unroll
            for (int mt = 0; mt < 2; mt++) {
                int m = mBase + mt * 16 + group;
                int w0 = m * 32 + (((2 * ks)     ^ (m & 7)) << 2) + tid4;
                int w2 = m * 32 + (((2 * ks + 1) ^ (m & 7)) << 2) + tid4;
                af[mt][0] = sA[w0];       af[mt][1] = sA[w0 + 256];
                af[mt][2] = sA[w2];       af[mt][3] = sA[w2 + 256];
            }
            #pragma unroll
            for (int nt = 0; nt < 4; nt++) {
                int n = nBase + nt * 8 + group;
                int v0 = n * 32 + (((2 * ks)     ^ (n & 7)) << 2) + tid4;
                int v1 = n * 32 + (((2 * ks + 1) ^ (n & 7)) << 2) + tid4;
                bf[nt][0] = sB[v0];       bf[nt][1] = sB[v1];
            }
            #pragma unroll
            for (int mt = 0; mt < 2; mt++)
                #pragma unroll
                for (int nt = 0; nt < 4; nt++)
                    mma8(acc[mt][nt], af[mt], bf[nt]);
        }
        __syncthreads();
    }
}

// ------------------------------------------------------------------
// K1: proj_x
// ------------------------------------------------------------------
__global__ void __launch_bounds__(256) k_proj(const float* __restrict__ x,
                                              const float* __restrict__ W0,
                                              const float* __restrict__ b0,
                                              const float* __restrict__ W1,
                                              const float* __restrict__ b1) {
    __shared__ float xs[8][64];
    __shared__ float hs[8][512];
    int b  = blockIdx.x >> 4;
    int t0 = (blockIdx.x & 15) * 8;
    int tid = threadIdx.x;

    for (int i = tid; i < 8 * 64; i += 256) {
        int tt = i >> 6, k = i & 63;
        xs[tt][k] = x[(b * (O_ + L_) + t0 + tt) * S_ + k];
    }
    __syncthreads();

    #pragma unroll
    for (int jj = 0; jj < 2; jj++) {
        int j = tid + jj * 256;
        float acc[8];
        float bj = b0[j];
        #pragma unroll
        for (int tt = 0; tt < 8; tt++) acc[tt] = bj;
        for (int k = 0; k < 64; k++) {
            float w = W0[j * 64 + k];
            #pragma unroll
            for (int tt = 0; tt < 8; tt++) acc[tt] += w * xs[tt][k];
        }
        #pragma unroll
        for (int tt = 0; tt < 8; tt++) hs[tt][j] = fmaxf(acc[tt], 0.0f);
    }
    __syncthreads();

    int n = tid;
    float acc2[8];
    float bn = b1[n];
    #pragma unroll
    for (int tt = 0; tt < 8; tt++) acc2[tt] = bn;
    for (int j = 0; j < 512; j++) {
        float w = W1[n * 512 + j];
        #pragma unroll
        for (int tt = 0; tt < 8; tt++) acc2[tt] += w * hs[tt][j];
    }
    #pragma unroll
    for (int tt = 0; tt < 8; tt++) g_p[(b * L_ + t0 + tt) * N_ + n] = acc2[tt];
}

// ------------------------------------------------------------------
// K2: silu -> depthwise conv -> silu, output pre-rounded to tf32.
// ------------------------------------------------------------------
__global__ void k_conv(const float* __restrict__ u,
                       const float* __restrict__ cw,
                       const float* __restrict__ cb) {
    int tok = blockIdx.x;
    int b = tok >> 7, l = tok & 127;
    int c = threadIdx.x;   // 0..287
    float acc = cb[c];
    #pragma unroll
    for (int k = 0; k < KC; k++) {
        int i = l - 1 + k;
        if (i >= 0 && i <= 126) {
            float v = (c < 256) ? g_p[((b << 7) + i) * N_ + c]
                                : u[(b * 256 + i) * U_ + (c - 256)];
            acc += cw[c * 4 + k] * siluf(v);
        }
    }
    g_old[tok * CDIM + c] = tf32rf(siluf(acc));
}

// ------------------------------------------------------------------
// K3a: tf32-round Wg rows DEL.. into g_wgt (float4 stream).
// ------------------------------------------------------------------
__global__ void k_wround(const float* __restrict__ Wg) {
    const float4* src = reinterpret_cast<const float4*>(Wg + (size_t)DEL * KDIM);
    float4* dst = reinterpret_cast<float4*>(g_wgt);
    int total = (WROWS * KDIM) / 4;   // 1,769,472
    for (int i = blockIdx.x * blockDim.x + threadIdx.x; i < total;
         i += gridDim.x * blockDim.x) {
        float4 v = src[i];
        dst[i] = make_float4(tf32rf(v.x), tf32rf(v.y), tf32rf(v.z), tf32rf(v.w));
    }
}

// ------------------------------------------------------------------
// K3b: Wc = Wdt @ Wg[0:64] (tf32-rounded), bc = Wdt@bg[0:64]+bdt; zero g_y.
// ------------------------------------------------------------------
__global__ void k_wcomb(const float* __restrict__ Wg, const float* __restrict__ bg,
                        const float* __restrict__ Wdt, const float* __restrict__ bdt) {
    __shared__ float sw[64];
    int n = blockIdx.x;       // 0..255
    int tid = threadIdx.x;    // 0..287
    if (tid < 64) sw[tid] = Wdt[n * 64 + tid];
    __syncthreads();
    float acc = 0.0f;
    #pragma unroll 8
    for (int d = 0; d < 64; d++) acc += sw[d] * Wg[d * KDIM + tid];
    g_wc[n * KDIM + tid] = tf32rf(acc);
    if (tid == 0) {
        float s = bdt[n];
        for (int d = 0; d < 64; d++) s += sw[d] * bg[d];
        g_bc[n] = s;
    }
    for (int i = blockIdx.x * blockDim.x + tid; i < TOK * S_; i += gridDim.x * blockDim.x)
        g_y[i] = 0.0f;
}

// ------------------------------------------------------------------
// K4: delta GEMM: g_dpre = old @ Wc^T  (M=2048, N=256)
// ------------------------------------------------------------------
__global__ void __launch_bounds__(256) k_gemm_delta() {
    __shared__ uint32_t sm[12288];
    uint32_t sbase = (uint32_t)__cvta_generic_to_shared(sm);
    int m0 = blockIdx.y * 128;
    int n0 = blockIdx.x * 64;
    int tid = threadIdx.x;
    int lane = tid & 31, wid = tid >> 5;
    int wm = wid >> 1, wn = wid & 1;
    int group = lane >> 2, tid4 = lane & 3;

    float acc[2][4][4];
    gemm_pipe(sm, sbase, &g_old[(size_t)m0 * KDIM], &g_wc[(size_t)n0 * KDIM], tid, acc);

    #pragma unroll
    for (int mt = 0; mt < 2; mt++) {
        int r0 = m0 + wm * 32 + mt * 16 + group;
        #pragma unroll
        for (int nt = 0; nt < 4; nt++) {
            int c = n0 + wn * 32 + nt * 8 + tid4 * 2;
            *reinterpret_cast<float2*>(&g_dpre[r0 * N_ + c]) =
                make_float2(acc[mt][nt][0], acc[mt][nt][1]);
            *reinterpret_cast<float2*>(&g_dpre[(r0 + 8) * N_ + c]) =
                make_float2(acc[mt][nt][2], acc[mt][nt][3]);
        }
    }
}

// ------------------------------------------------------------------
// K5: delta transform: softplus -> dA, coeff.
// ------------------------------------------------------------------
__global__ void k_dtrans(const float* __restrict__ A) {
    int idx0 = blockIdx.x * blockDim.x + threadIdx.x;
    for (int idx = idx0; idx < TOK * N_; idx += gridDim.x * blockDim.x) {
        int n = idx & 255;
        float acc = g_dpre[idx] + g_bc[n];
        float sp = fmaxf(acc, 0.0f) + log1pf(expf(-fabsf(acc)));
        float a = A[n];
        float an = (a > 0.0f) ? -a : -expm1f(a);
        float dA = expf(sp * an);
        g_dA[idx] = dA;
        g_coeff[idx] = (dA - 1.0f) / an;
    }
}

// ------------------------------------------------------------------
// K6: Bm GEMM + fused Bu epilogue. BN=64: warp wn owns one n (32 u-cols).
// ------------------------------------------------------------------
__global__ void __launch_bounds__(256) k_gemm_bu(const float* __restrict__ bg,
                                                 const float* __restrict__ u) {
    __shared__ uint32_t sm[12288];
    uint32_t sbase = (uint32_t)__cvta_generic_to_shared(sm);
    int m0 = blockIdx.y * 128;
    int n0 = blockIdx.x * 64;      // local Bm col
    int tid = threadIdx.x;
    int lane = tid & 31, wid = tid >> 5;
    int wm = wid >> 1, wn = wid & 1;
    int group = lane >> 2, tid4 = lane & 3;

    float acc[2][4][4];
    gemm_pipe(sm, sbase, &g_old[(size_t)m0 * KDIM], &g_wgt[(size_t)n0 * KDIM], tid, acc);

    int nb = blockIdx.x * 2 + wn;
    const float* bgp = &bg[DEL + n0 + wn * 32];

    #pragma unroll
    for (int mt = 0; mt < 2; mt++) {
        int r0 = m0 + wm * 32 + mt * 16 + group;
        int r1 = r0 + 8;
        const float* u0p = &u[((r0 >> 7) * 256 + 127 + (r0 & 127)) * U_];
        const float* u1p = &u[((r1 >> 7) * 256 + 127 + (r1 & 127)) * U_];
        float s0 = 0.0f, s1 = 0.0f;
        #pragma unroll
        for (int nt = 0; nt < 4; nt++) {
            int uu = nt * 8 + tid4 * 2;
            float bg0 = bgp[uu], bg1 = bgp[uu + 1];
            s0 += (acc[mt][nt][0] + bg0) * u0p[uu] + (acc[mt][nt][1] + bg1) * u0p[uu + 1];
            s1 += (acc[mt][nt][2] + bg0) * u1p[uu] + (acc[mt][nt][3] + bg1) * u1p[uu + 1];
        }
        s0 += __shfl_xor_sync(0xffffffffu, s0, 1);
        s0 += __shfl_xor_sync(0xffffffffu, s0, 2);
        s1 += __shfl_xor_sync(0xffffffffu, s1, 1);
        s1 += __shfl_xor_sync(0xffffffffu, s1, 2);
        if (tid4 == 0) {
            g_buraw[r0 * N_ + nb] = s0;
            g_buraw[r1 * N_ + nb] = s1;
        }
    }
}

// ------------------------------------------------------------------
// K7: sequential scan.
// ------------------------------------------------------------------
__global__ void k_scan() {
    int b = blockIdx.x;
    int n = threadIdx.x;
    float z = g_p[((b << 7) + 127) * N_ + n];
    for (int t0 = 0; t0 < L_; t0 += 8) {
        float da[8], bu[8], cf[8];
        #pragma unroll
        for (int q = 0; q < 8; q++) {
            int idx = ((b << 7) + t0 + q) * N_ + n;
            da[q] = g_dA[idx];
            bu[q] = g_buraw[idx];
            cf[q] = g_coeff[idx];
        }
        #pragma unroll
        for (int q = 0; q < 8; q++) {
            z = z * da[q] + cf[q] * bu[q];
            g_z[((b << 7) + t0 + q) * N_ + n] = z;
        }
    }
}

// ------------------------------------------------------------------
// K8: Cm GEMM + fused y epilogue. 8 x BN=64 tiles per block; y in regs.
// ------------------------------------------------------------------
__global__ void __launch_bounds__(256) k_gemm_y(const float* __restrict__ bg) {
    __shared__ uint32_t sm[12288];
    uint32_t sbase = (uint32_t)__cvta_generic_to_shared(sm);
    int m0 = blockIdx.y * 128;
    int cb0 = blockIdx.x * 512;    // local Cm col base
    int tid = threadIdx.x;
    int lane = tid & 31, wid = tid >> 5;
    int wm = wid >> 1, wn = wid & 1;
    int group = lane >> 2, tid4 = lane & 3;

    float yacc[2][4][4];
    #pragma unroll
    for (int i = 0; i < 2; i++)
        #pragma unroll
        for (int j = 0; j < 4; j++)
            #pragma unroll
            for (int q = 0; q < 4; q++) yacc[i][j][q] = 0.0f;

    #pragma unroll 1
    for (int tt = 0; tt < 8; tt++) {
        int cb = cb0 + tt * 64;
        float acc[2][4][4];
        gemm_pipe(sm, sbase, &g_old[(size_t)m0 * KDIM],
                  &g_wgt[(size_t)(NBM + cb) * KDIM], tid, acc);
        int nidx = (cb + wn * 32) >> 6;
        const float* bgp = &bg[DEL + NBM + cb + wn * 32];
        #pragma unroll
        for (int mt = 0; mt < 2; mt++) {
            int r0 = m0 + wm * 32 + mt * 16 + group;
            float z0 = g_z[r0 * N_ + nidx];
            float z1 = g_z[(r0 + 8) * N_ + nidx];
            #pragma unroll
            for (int nt = 0; nt < 4; nt++) {
                int cc = nt * 8 + tid4 * 2;
                float bg0 = bgp[cc], bg1 = bgp[cc + 1];
                yacc[mt][nt][0] += (acc[mt][nt][0] + bg0) * z0;
                yacc[mt][nt][1] += (acc[mt][nt][1] + bg1) * z0;
                yacc[mt][nt][2] += (acc[mt][nt][2] + bg0) * z1;
                yacc[mt][nt][3] += (acc[mt][nt][3] + bg1) * z1;
            }
        }
    }

    #pragma unroll
    for (int mt = 0; mt < 2; mt++) {
        int r0 = m0 + wm * 32 + mt * 16 + group;
        #pragma unroll
        for (int nt = 0; nt < 4; nt++) {
            int s = (wn * 32 + nt * 8 + tid4 * 2) & 63;
            atomicAdd(&g_y[r0 * S_ + s],           yacc[mt][nt][0]);
            atomicAdd(&g_y[r0 * S_ + s + 1],       yacc[mt][nt][1]);
            atomicAdd(&g_y[(r0 + 8) * S_ + s],     yacc[mt][nt][2]);
            atomicAdd(&g_y[(r0 + 8) * S_ + s + 1], yacc[mt][nt][3]);
        }
    }
}

// ------------------------------------------------------------------
// K9: y finalize.
// ------------------------------------------------------------------
__global__ void k_yfin(const float* __restrict__ x, float* __restrict__ out) {
    __shared__ float red[2];
    int tok = blockIdx.x;
    int b = tok >> 7, t = tok & 127;
    int s = threadIdx.x;   // 0..63
    float yv = g_y[tok * S_ + s];
    out[1 + ((t << 4) + b) * S_ + s] = yv;
    float diff = yv - x[(b * 256 + 128 + t) * S_ + s];
    float v = diff * diff;
    #pragma unroll
    for (int o = 16; o > 0; o >>= 1) v += __shfl_down_sync(0xffffffffu, v, o);
    if ((s & 31) == 0) red[s >> 5] = v;
    __syncthreads();
    if (s == 0) g_part[tok] = red[0] + red[1];
}

// ------------------------------------------------------------------
// K10: loss reduction.
// ------------------------------------------------------------------
__global__ void k_loss(float* __restrict__ out) {
    __shared__ float red[256];
    float v = 0.0f;
    for (int i = threadIdx.x; i < TOK; i += 256) v += g_part[i];
    red[threadIdx.x] = v;
    __syncthreads();
    for (int st = 128; st > 0; st >>= 1) {
        if (threadIdx.x < st) red[threadIdx.x] += red[threadIdx.x + st];
        __syncthreads();
    }
    if (threadIdx.x == 0) out[0] = red[0] / (float)(B_ * S_ * L_);
}

// ------------------------------------------------------------------
extern "C" void kernel_launch(void* const* d_in, const int* in_sizes, int n_in,
                              void* d_out, int out_size) {
    const float* x   = (const float*)d_in[0];
    const float* u   = (const float*)d_in[1];
    const float* A   = (const float*)d_in[2];
    const float* W0  = (const float*)d_in[3];
    const float* b0  = (const float*)d_in[4];
    const float* W1  = (const float*)d_in[5];
    const float* b1  = (const float*)d_in[6];
    const float* cw  = (const float*)d_in[7];
    const float* cb  = (const float*)d_in[8];
    const float* Wg  = (const float*)d_in[9];
    const float* bg  = (const float*)d_in[10];
    const float* Wdt = (const float*)d_in[11];
    const float* bdt = (const float*)d_in[12];
    float* out = (float*)d_out;

    k_proj<<<256, 256>>>(x, W0, b0, W1, b1);
    k_conv<<<TOK, CDIM>>>(u, cw, cb);
    k_wround<<<1024, 256>>>(Wg);
    k_wcomb<<<N_, CDIM>>>(Wg, bg, Wdt, bdt);
    k_gemm_delta<<<dim3(4, 16), 256>>>();
    k_dtrans<<<512, 256>>>(A);
    k_gemm_bu<<<dim3(NBM / 64, 16), 256>>>(bg, u);
    k_scan<<<B_, N_>>>();
    k_gemm_y<<<dim3(NCM / 512, 16), 256>>>(bg);
    k_yfin<<<TOK, S_>>>(x, out);
    k_loss<<<1, 256>>>(out);
}